// round 3
// baseline (speedup 1.0000x reference)
#include <cuda_runtime.h>
#include <math.h>

#define BATCH 2
#define SEQ   4096
#define DIM   128
#define HEADS 2
#define DHEAD 64
#define NROWS (BATCH*SEQ)        // 8192
#define ATTN_SCALE 0.125f        // DHEAD^-0.5

typedef unsigned long long u64;

// ---------------- device scratch (no runtime allocation) ----------------
__device__ float g_Wqkv[384*128];
__device__ float g_W1[128*128];
__device__ float g_W2[128*128];
__device__ float g_Q[NROWS*128];     // [b*n][128]  (both heads contiguous)
__device__ float g_K[NROWS*128];
__device__ float g_V[NROWS*128];
__device__ float g_sq[NROWS];
__device__ float g_part[BATCH*64*64];          // per-block dist partial sums
__device__ float g_cspe;                       // 1/(2*sigma_spe^2)
__device__ float g_cspa;                       // 1/(2*sigma_spa^2)
__device__ float g_DOTS[67108864];             // [b][h][i][j]  268MB
__device__ float g_M[BATCH*HEADS*SEQ];         // row max
__device__ float g_L[BATCH*HEADS*SEQ];         // 1/row sumexp
__device__ float g_AO[NROWS*128];              // attention output
__device__ float g_H1[NROWS*128];              // FF hidden

// ---------------- packed f32x2 helpers (FFMA2 path) ---------------------
__device__ __forceinline__ u64 pk2(float lo, float hi) {
    u64 r; asm("mov.b64 %0, {%1, %2};" : "=l"(r) : "f"(lo), "f"(hi)); return r;
}
__device__ __forceinline__ void fma2(u64& d, u64 a, u64 b) {
    asm("fma.rn.f32x2 %0, %1, %2, %0;" : "+l"(d) : "l"(a), "l"(b));
}
__device__ __forceinline__ float2 upk2(u64 v) {
    float lo, hi; asm("mov.b64 {%0, %1}, %2;" : "=f"(lo), "=f"(hi) : "l"(v));
    return make_float2(lo, hi);
}

// ---------------- GEMM micro-tile (BM=BN=64, BK=32, 256 thr) ------------
// A-operand smem: u64 pairs (a,a) pre-duplicated at load time.
// B-operand smem: plain floats; adjacent pairs read directly as u64.
// Inner loop: 2 LDS.128 (A) + 1 LDS.128 (B) + 8 FFMA2, zero packing movs.
#define FMA_TILE_G(ACC, SA, SB) do {                                    \
    ulonglong2 _aa0 = *(const ulonglong2*)&SA[kk][ty*4];                \
    ulonglong2 _aa1 = *(const ulonglong2*)&SA[kk][ty*4+2];              \
    ulonglong2 _bb  = *(const ulonglong2*)&SB[kk][tx*4];                \
    fma2(ACC[0][0], _aa0.x, _bb.x); fma2(ACC[0][1], _aa0.x, _bb.y);     \
    fma2(ACC[1][0], _aa0.y, _bb.x); fma2(ACC[1][1], _aa0.y, _bb.y);     \
    fma2(ACC[2][0], _aa1.x, _bb.x); fma2(ACC[2][1], _aa1.x, _bb.y);     \
    fma2(ACC[3][0], _aa1.y, _bb.x); fma2(ACC[3][1], _aa1.y, _bb.y);     \
} while(0)

#define MMA_LOOP32(ACC) { _Pragma("unroll") for (int kk=0;kk<32;kk++){ FMA_TILE_G(ACC, As, Bs); } }

// unpack ACC[4][2] (f32x2) -> F[4][4] scalars
#define UNPACK_ACC(ACC, F) do {                                         \
    _Pragma("unroll")                                                   \
    for (int _i=0;_i<4;_i++) {                                          \
        float2 _t0 = upk2(ACC[_i][0]), _t1 = upk2(ACC[_i][1]);          \
        F[_i][0]=_t0.x; F[_i][1]=_t0.y; F[_i][2]=_t1.x; F[_i][3]=_t1.y; \
    }                                                                   \
} while(0)

// A loader: writes duplicated (v,v) u64 pairs. lr=tid>>2 row, lk=(tid&3)*8
#define LOAD_TA(SM, BASEPTR) do {                                       \
    const float* _p = (BASEPTR) + (size_t)lr*128 + lk;                  \
    float4 _t0 = *(const float4*)_p;                                    \
    float4 _t1 = *(const float4*)(_p+4);                                \
    SM[lk+0][lr]=pk2(_t0.x,_t0.x); SM[lk+1][lr]=pk2(_t0.y,_t0.y);       \
    SM[lk+2][lr]=pk2(_t0.z,_t0.z); SM[lk+3][lr]=pk2(_t0.w,_t0.w);       \
    SM[lk+4][lr]=pk2(_t1.x,_t1.x); SM[lk+5][lr]=pk2(_t1.y,_t1.y);       \
    SM[lk+6][lr]=pk2(_t1.z,_t1.z); SM[lk+7][lr]=pk2(_t1.w,_t1.w);       \
} while(0)

// B loader: plain transpose-to-[k][col] floats
#define LOAD_TB(SM, BASEPTR) do {                                       \
    const float* _p = (BASEPTR) + (size_t)lr*128 + lk;                  \
    float4 _t0 = *(const float4*)_p;                                    \
    float4 _t1 = *(const float4*)(_p+4);                                \
    SM[lk+0][lr]=_t0.x; SM[lk+1][lr]=_t0.y; SM[lk+2][lr]=_t0.z; SM[lk+3][lr]=_t0.w; \
    SM[lk+4][lr]=_t1.x; SM[lk+5][lr]=_t1.y; SM[lk+6][lr]=_t1.z; SM[lk+7][lr]=_t1.w; \
} while(0)

// ---------------- 1. weight-norm preprocessing --------------------------
__global__ void prep_weights(const float* __restrict__ vq, const float* __restrict__ gq,
                             const float* __restrict__ v1, const float* __restrict__ g1,
                             const float* __restrict__ v2, const float* __restrict__ g2) {
    int warp = (blockIdx.x*blockDim.x + threadIdx.x) >> 5;
    int lane = threadIdx.x & 31;
    if (warp >= 640) return;
    const float* v; const float* g; float* w; int r;
    if (warp < 384)      { v=vq; g=gq; w=g_Wqkv; r=warp; }
    else if (warp < 512) { v=v1; g=g1; w=g_W1;   r=warp-384; }
    else                 { v=v2; g=g2; w=g_W2;   r=warp-512; }
    float4 x4 = ((const float4*)(v + (size_t)r*128))[lane];
    float s = x4.x*x4.x + x4.y*x4.y + x4.z*x4.z + x4.w*x4.w;
    #pragma unroll
    for (int o=16;o;o>>=1) s += __shfl_xor_sync(0xffffffffu, s, o);
    float rn = g[r] / sqrtf(s);
    float4 o4 = make_float4(x4.x*rn, x4.y*rn, x4.z*rn, x4.w*rn);
    ((float4*)(w + (size_t)r*128))[lane] = o4;
}

// ---------------- 2. qkv projection  Y = X @ Wqkv^T + b -----------------
__global__ void qkv_gemm(const float* __restrict__ x, const float* __restrict__ bias) {
    __shared__ u64   As[32][64];
    __shared__ float Bs[32][64];
    int rt0 = blockIdx.y*64;          // row tile of 8192
    int ct0 = blockIdx.x*64;          // col tile of 384
    int tid = threadIdx.x;
    int ty = tid>>4, tx = tid&15;
    int lr = tid>>2, lk = (tid&3)*8;
    u64 acc[4][2] = {};
    #pragma unroll 1
    for (int kc=0; kc<4; kc++) {
        int k0 = kc*32;
        LOAD_TA(As, x      + (size_t)rt0*128 + k0);
        LOAD_TB(Bs, g_Wqkv + (size_t)ct0*128 + k0);
        __syncthreads();
        MMA_LOOP32(acc);
        __syncthreads();
    }
    float f[4][4]; UNPACK_ACC(acc, f);
    int c0 = ct0 + tx*4;
    float b0 = bias[c0], b1 = bias[c0+1], b2 = bias[c0+2], b3 = bias[c0+3];
    float* base = (c0 < 128) ? g_Q : ((c0 < 256) ? g_K : g_V);
    int col = c0 & 127;
    #pragma unroll
    for (int i=0;i<4;i++) {
        int row = rt0 + ty*4 + i;
        float4 o = make_float4(f[i][0]+b0, f[i][1]+b1, f[i][2]+b2, f[i][3]+b3);
        *(float4*)(base + (size_t)row*128 + col) = o;
    }
}

// ---------------- 3. row squared norms ----------------------------------
__global__ void sq_kernel(const float* __restrict__ x) {
    int warp = (blockIdx.x*blockDim.x + threadIdx.x) >> 5;
    int lane = threadIdx.x & 31;
    if (warp >= NROWS) return;
    float4 v4 = ((const float4*)(x + (size_t)warp*128))[lane];
    float s = v4.x*v4.x + v4.y*v4.y + v4.z*v4.z + v4.w*v4.w;
    #pragma unroll
    for (int o=16;o;o>>=1) s += __shfl_xor_sync(0xffffffffu, s, o);
    if (lane==0) g_sq[warp] = s;
}

// ---------------- 4. sigma_spe partials (triangular gram) ---------------
__global__ void sigma_kernel(const float* __restrict__ x) {
    int jt = blockIdx.x, it = blockIdx.y, b = blockIdx.z;
    int bid = (blockIdx.z*64 + blockIdx.y)*64 + blockIdx.x;
    __shared__ u64   As[32][64];
    __shared__ float Bs[32][64];
    __shared__ float red[256];
    int tid = threadIdx.x;
    if (jt < it) { if (tid==0) g_part[bid] = 0.0f; return; }
    int ty = tid>>4, tx = tid&15;
    int lr = tid>>2, lk = (tid&3)*8;
    u64 acc[4][2] = {};
    const float* xb = x + (size_t)b*SEQ*128;
    #pragma unroll 1
    for (int kc=0; kc<4; kc++) {
        int k0 = kc*32;
        LOAD_TA(As, xb + (size_t)it*64*128 + k0);
        LOAD_TB(Bs, xb + (size_t)jt*64*128 + k0);
        __syncthreads();
        MMA_LOOP32(acc);
        __syncthreads();
    }
    float f[4][4]; UNPACK_ACC(acc, f);
    float w = (jt==it) ? 1.0f : 2.0f;
    float sqi[4], sqj[4];
    #pragma unroll
    for (int i=0;i<4;i++) sqi[i] = g_sq[b*SEQ + it*64 + ty*4 + i];
    #pragma unroll
    for (int j=0;j<4;j++) sqj[j] = g_sq[b*SEQ + jt*64 + tx*4 + j];
    float lsum = 0.0f;
    #pragma unroll
    for (int i=0;i<4;i++)
        #pragma unroll
        for (int j=0;j<4;j++) {
            float d2 = sqi[i] + sqj[j] - 2.0f*f[i][j];
            lsum += sqrtf(fmaxf(d2, 0.0f));
        }
    red[tid] = lsum * w;
    __syncthreads();
    for (int o=128;o;o>>=1) { if (tid<o) red[tid] += red[tid+o]; __syncthreads(); }
    if (tid==0) g_part[bid] = red[0];
}

// ---------------- 5. finalize sigmas (deterministic) --------------------
__global__ void finalize_kernel() {
    __shared__ double rs[256];
    int tid = threadIdx.x;
    double s = 0.0;
    for (int i=tid; i<BATCH*64*64; i+=256) s += (double)g_part[i];
    rs[tid] = s; __syncthreads();
    for (int o=128;o;o>>=1) { if (tid<o) rs[tid] += rs[tid+o]; __syncthreads(); }
    double spe_total = rs[0];
    __syncthreads();
    // spatial sigma: weighted sum over (dx,dy) offsets on 64x64 grid
    double sp = 0.0;
    for (int idx=tid; idx<127*127; idx+=256) {
        int dx = idx/127 - 63, dy = idx%127 - 63;
        double wgt = (double)((64-abs(dx))*(64-abs(dy)));
        sp += wgt * (double)sqrtf((float)(dx*dx + dy*dy));
    }
    rs[tid] = sp; __syncthreads();
    for (int o=128;o;o>>=1) { if (tid<o) rs[tid] += rs[tid+o]; __syncthreads(); }
    if (tid==0) {
        double nn = (double)SEQ * (double)SEQ;
        double sigma_spe = spe_total / ((double)BATCH * nn);
        double sigma_spa = rs[0] / nn;
        g_cspe = (float)(1.0 / (2.0 * sigma_spe * sigma_spe));
        g_cspa = (float)(1.0 / (2.0 * sigma_spa * sigma_spa));
    }
}

// ---------------- 6. masked logits: gram + QK^T fused (K=256) -----------
__global__ void dots_kernel(const float* __restrict__ x) {
    int jt = blockIdx.x, it = blockIdx.y, b = blockIdx.z;
    __shared__ u64   As[32][64];
    __shared__ float Bs[32][64];
    int tid = threadIdx.x;
    int ty = tid>>4, tx = tid&15;
    int lr = tid>>2, lk = (tid&3)*8;
    u64 accG[4][2] = {}, acc0[4][2] = {}, acc1[4][2] = {};
    const float* xb = x   + (size_t)b*SEQ*128;
    const float* qb = g_Q + (size_t)b*SEQ*128;
    const float* kb = g_K + (size_t)b*SEQ*128;
    #pragma unroll 1
    for (int kc=0; kc<8; kc++) {
        const float* Ab = (kc<4) ? xb : qb;
        const float* Bb = (kc<4) ? xb : kb;
        int k0 = (kc<4) ? kc*32 : (kc-4)*32;
        LOAD_TA(As, Ab + (size_t)it*64*128 + k0);
        LOAD_TB(Bs, Bb + (size_t)jt*64*128 + k0);
        __syncthreads();
        if (kc < 4)      { MMA_LOOP32(accG); }
        else if (kc < 6) { MMA_LOOP32(acc0); }
        else             { MMA_LOOP32(acc1); }
        __syncthreads();
    }
    float fG[4][4], f0[4][4], f1[4][4];
    UNPACK_ACC(accG, fG); UNPACK_ACC(acc0, f0); UNPACK_ACC(acc1, f1);
    float cspe = g_cspe, cspa = g_cspa;
    int i0 = it*64 + ty*4, j0 = jt*64 + tx*4;
    float sqi[4], sqj[4];
    #pragma unroll
    for (int i=0;i<4;i++) sqi[i] = g_sq[b*SEQ + i0 + i];
    #pragma unroll
    for (int j=0;j<4;j++) sqj[j] = g_sq[b*SEQ + j0 + j];
    #pragma unroll
    for (int i=0;i<4;i++) {
        int gi = i0 + i;
        int ix = gi >> 6, iy = gi & 63;
        float o0[4], o1[4];
        #pragma unroll
        for (int j=0;j<4;j++) {
            int gj = j0 + j;
            float d2 = sqi[i] + sqj[j] - 2.0f*fG[i][j];
            float spe = __expf(-sqrtf(fmaxf(d2, 0.0f)) * cspe);
            int dx = ix - (gj >> 6), dy = iy - (gj & 63);
            float spa = __expf(-sqrtf((float)(dx*dx + dy*dy)) * cspa);
            float m = spe * spa * ATTN_SCALE;
            o0[j] = f0[i][j] * m;
            o1[j] = f1[i][j] * m;
        }
        size_t r0 = ((size_t)(b*2 + 0)*SEQ + gi)*SEQ + j0;
        size_t r1 = ((size_t)(b*2 + 1)*SEQ + gi)*SEQ + j0;
        *(float4*)&g_DOTS[r0] = make_float4(o0[0],o0[1],o0[2],o0[3]);
        *(float4*)&g_DOTS[r1] = make_float4(o1[0],o1[1],o1[2],o1[3]);
    }
}

// ---------------- 7. softmax row stats ----------------------------------
__global__ void stats_kernel() {
    int r = blockIdx.x;                       // 0..16383
    size_t base = (size_t)r * SEQ;
    int tid = threadIdx.x;
    __shared__ float red[256];
    float v[16];
    float mx = -1e30f;
    #pragma unroll
    for (int s=0;s<16;s++) { v[s] = g_DOTS[base + (size_t)s*256 + tid]; mx = fmaxf(mx, v[s]); }
    red[tid] = mx; __syncthreads();
    for (int o=128;o;o>>=1) { if (tid<o) red[tid] = fmaxf(red[tid], red[tid+o]); __syncthreads(); }
    mx = red[0];
    __syncthreads();
    float sm = 0.0f;
    #pragma unroll
    for (int s=0;s<16;s++) sm += __expf(v[s] - mx);
    red[tid] = sm; __syncthreads();
    for (int o=128;o;o>>=1) { if (tid<o) red[tid] += red[tid+o]; __syncthreads(); }
    if (tid==0) { g_M[r] = mx; g_L[r] = 1.0f / red[0]; }
}

// ---------------- 8. out = softmax(dots) @ V ----------------------------
__global__ void pv_kernel() {
    int it = blockIdx.x;     // 0..63
    int h  = blockIdx.y;     // 0..1
    int b  = blockIdx.z;     // 0..1
    __shared__ u64   Ps[64][64];   // [j][i] duplicated pairs (32KB)
    __shared__ float Vs[64][64];   // [j][c] (16KB)
    int tid = threadIdx.x;
    int ty = tid>>4, tx = tid&15;
    int lr = tid>>2;               // 0..63
    int lq = (tid&3)*16;           // 0,16,32,48
    u64 acc[4][2] = {};
    int bh = b*2 + h;
    size_t drow = ((size_t)bh*SEQ + it*64 + lr)*SEQ;
    float mrow = g_M[bh*SEQ + it*64 + lr];
    const float* vbase = g_V + (size_t)b*SEQ*128 + h*64;
    #pragma unroll 1
    for (int jc=0; jc<64; jc++) {
        int j0 = jc*64;
        const float* dp = g_DOTS + drow + j0 + lq;
        float4 p0 = *(const float4*)dp;
        float4 p1 = *(const float4*)(dp+4);
        float4 p2 = *(const float4*)(dp+8);
        float4 p3 = *(const float4*)(dp+12);
        float e;
        e=__expf(p0.x-mrow); Ps[lq+ 0][lr]=pk2(e,e);
        e=__expf(p0.y-mrow); Ps[lq+ 1][lr]=pk2(e,e);
        e=__expf(p0.z-mrow); Ps[lq+ 2][lr]=pk2(e,e);
        e=__expf(p0.w-mrow); Ps[lq+ 3][lr]=pk2(e,e);
        e=__expf(p1.x-mrow); Ps[lq+ 4][lr]=pk2(e,e);
        e=__expf(p1.y-mrow); Ps[lq+ 5][lr]=pk2(e,e);
        e=__expf(p1.z-mrow); Ps[lq+ 6][lr]=pk2(e,e);
        e=__expf(p1.w-mrow); Ps[lq+ 7][lr]=pk2(e,e);
        e=__expf(p2.x-mrow); Ps[lq+ 8][lr]=pk2(e,e);
        e=__expf(p2.y-mrow); Ps[lq+ 9][lr]=pk2(e,e);
        e=__expf(p2.z-mrow); Ps[lq+10][lr]=pk2(e,e);
        e=__expf(p2.w-mrow); Ps[lq+11][lr]=pk2(e,e);
        e=__expf(p3.x-mrow); Ps[lq+12][lr]=pk2(e,e);
        e=__expf(p3.y-mrow); Ps[lq+13][lr]=pk2(e,e);
        e=__expf(p3.z-mrow); Ps[lq+14][lr]=pk2(e,e);
        e=__expf(p3.w-mrow); Ps[lq+15][lr]=pk2(e,e);
        const float* vp = vbase + (size_t)(j0 + lr)*128 + lq;
        *(float4*)&Vs[lr][lq+ 0] = *(const float4*)vp;
        *(float4*)&Vs[lr][lq+ 4] = *(const float4*)(vp+4);
        *(float4*)&Vs[lr][lq+ 8] = *(const float4*)(vp+8);
        *(float4*)&Vs[lr][lq+12] = *(const float4*)(vp+12);
        __syncthreads();
        #pragma unroll
        for (int kk=0;kk<64;kk++) { FMA_TILE_G(acc, Ps, Vs); }
        __syncthreads();
    }
    float f[4][4]; UNPACK_ACC(acc, f);
    #pragma unroll
    for (int i=0;i<4;i++) {
        int gi = it*64 + ty*4 + i;
        float li = g_L[bh*SEQ + gi];
        float4 o = make_float4(f[i][0]*li, f[i][1]*li, f[i][2]*li, f[i][3]*li);
        *(float4*)(g_AO + ((size_t)b*SEQ + gi)*128 + h*64 + tx*4) = o;
    }
}

// ---------------- 9/10. FeedForward GEMMs -------------------------------
__device__ __forceinline__ float gelu_exact(float v) { return v * normcdff(v); }

__global__ void ff_gemm(int stage, const float* __restrict__ bias, float* __restrict__ out_final) {
    __shared__ u64   As[32][64];
    __shared__ float Bs[32][64];
    const float* A = (stage==0) ? g_AO : g_H1;
    const float* W = (stage==0) ? g_W1 : g_W2;
    float* out     = (stage==0) ? g_H1 : out_final;
    int rt0 = blockIdx.y*64;
    int ct0 = blockIdx.x*64;
    int tid = threadIdx.x;
    int ty = tid>>4, tx = tid&15;
    int lr = tid>>2, lk = (tid&3)*8;
    u64 acc[4][2] = {};
    #pragma unroll 1
    for (int kc=0; kc<4; kc++) {
        int k0 = kc*32;
        LOAD_TA(As, A + (size_t)rt0*128 + k0);
        LOAD_TB(Bs, W + (size_t)ct0*128 + k0);
        __syncthreads();
        MMA_LOOP32(acc);
        __syncthreads();
    }
    float f[4][4]; UNPACK_ACC(acc, f);
    int c0 = ct0 + tx*4;
    float b0 = bias[c0], b1 = bias[c0+1], b2 = bias[c0+2], b3 = bias[c0+3];
    #pragma unroll
    for (int i=0;i<4;i++) {
        int row = rt0 + ty*4 + i;
        float v0 = f[i][0]+b0, v1 = f[i][1]+b1, v2 = f[i][2]+b2, v3 = f[i][3]+b3;
        if (stage==0) { v0=gelu_exact(v0); v1=gelu_exact(v1); v2=gelu_exact(v2); v3=gelu_exact(v3); }
        *(float4*)(out + (size_t)row*128 + c0) = make_float4(v0,v1,v2,v3);
    }
}

// ---------------- launch ------------------------------------------------
extern "C" void kernel_launch(void* const* d_in, const int* in_sizes, int n_in,
                              void* d_out, int out_size) {
    (void)in_sizes; (void)n_in; (void)out_size;
    const float* x     = (const float*)d_in[0];
    const float* v_qkv = (const float*)d_in[1];
    const float* gq    = (const float*)d_in[2];
    const float* b_qkv = (const float*)d_in[3];
    const float* v_ff1 = (const float*)d_in[4];
    const float* g_ff1 = (const float*)d_in[5];
    const float* b_ff1 = (const float*)d_in[6];
    const float* v_ff2 = (const float*)d_in[7];
    const float* g_ff2 = (const float*)d_in[8];
    const float* b_ff2 = (const float*)d_in[9];
    float* out = (float*)d_out;

    prep_weights<<<80, 256>>>(v_qkv, gq, v_ff1, g_ff1, v_ff2, g_ff2);
    qkv_gemm<<<dim3(6, 128), 256>>>(x, b_qkv);
    sq_kernel<<<1024, 256>>>(x);
    sigma_kernel<<<dim3(64, 64, BATCH), 256>>>(x);
    finalize_kernel<<<1, 256>>>();
    dots_kernel<<<dim3(64, 64, BATCH), 256>>>(x);
    stats_kernel<<<BATCH*HEADS*SEQ, 256>>>();
    pv_kernel<<<dim3(64, HEADS, BATCH), 256>>>();
    ff_gemm<<<dim3(2, 128), 256>>>(0, b_ff1, nullptr);
    ff_gemm<<<dim3(2, 128), 256>>>(1, b_ff2, out);
}

// round 6
// speedup vs baseline: 1.4177x; 1.4177x over previous
#include <cuda_runtime.h>
#include <math.h>

#define BATCH 2
#define SEQ   4096
#define HEADS 2
#define NROWS (BATCH*SEQ)        // 8192
#define ATTN_SCALE 0.125f

typedef unsigned long long u64;

// ---------------- device scratch (no runtime allocation) ----------------
__device__ float g_Wqkv[384*128];
__device__ float g_W1[128*128];
__device__ float g_W2[128*128];
__device__ float g_Q[NROWS*128];
__device__ float g_K[NROWS*128];
__device__ float g_V[NROWS*128];
__device__ float g_sq[NROWS];
__device__ float g_part[BATCH*32*32];          // per-tile dist partial sums
__device__ float g_cspe;                       // 1/(2*sigma_spe^2)
__device__ float g_cspa;                       // 1/(2*sigma_spa^2)
__device__ float g_DIST[(size_t)BATCH*SEQ*SEQ];   // 134MB pairwise dist
__device__ float g_DOTS[(size_t)BATCH*HEADS*SEQ*SEQ]; // 268MB masked logits
__device__ float g_M[BATCH*HEADS*SEQ];
__device__ float g_L[BATCH*HEADS*SEQ];
__device__ float g_AO[NROWS*128];
__device__ float g_H1[NROWS*128];

// ---------------- packed f32x2 helpers ----------------------------------
__device__ __forceinline__ u64 pk2(float lo, float hi) {
    u64 r; asm("mov.b64 %0, {%1, %2};" : "=l"(r) : "f"(lo), "f"(hi)); return r;
}
__device__ __forceinline__ void fma2(u64& d, u64 a, u64 b) {
    asm("fma.rn.f32x2 %0, %1, %2, %0;" : "+l"(d) : "l"(a), "l"(b));
}
__device__ __forceinline__ float2 upk2(u64 v) {
    float lo, hi; asm("mov.b64 {%0, %1}, %2;" : "=f"(lo), "=f"(hi) : "l"(v));
    return make_float2(lo, hi);
}

// ======== 128x128 tile, BK=16, 256 threads, 8x8 micro-tile ==============
// tx = tid&15 (col group), ty = tid>>4 (row group)
// loader: lr = tid>>1 (row 0..127), lk = (tid&1)*8
#define TDECL  int tid=threadIdx.x; int tx=tid&15, ty=tid>>4; int lr=tid>>1, lk=(tid&1)*8

#define LOAD_TILE(SM, BASEPTR) do {                                     \
    const float* _p = (BASEPTR) + (size_t)lr*128 + lk;                  \
    float4 _t0 = *(const float4*)_p;                                    \
    float4 _t1 = *(const float4*)(_p+4);                                \
    SM[lk+0][lr]=_t0.x; SM[lk+1][lr]=_t0.y; SM[lk+2][lr]=_t0.z; SM[lk+3][lr]=_t0.w; \
    SM[lk+4][lr]=_t1.x; SM[lk+5][lr]=_t1.y; SM[lk+6][lr]=_t1.z; SM[lk+7][lr]=_t1.w; \
} while(0)

// 8x8 inner step: A scalar+dup-mov, B natural packed pairs. 32 FFMA2.
#define FMA_KK8(ACC) do {                                               \
    float4 _a0 = *(const float4*)&As[kk][ty*8];                         \
    float4 _a1 = *(const float4*)&As[kk][ty*8+4];                       \
    ulonglong2 _b0 = *(const ulonglong2*)&Bs[kk][tx*8];                 \
    ulonglong2 _b1 = *(const ulonglong2*)&Bs[kk][tx*8+4];               \
    u64 _d;                                                             \
    _d=pk2(_a0.x,_a0.x); fma2(ACC[0][0],_d,_b0.x); fma2(ACC[0][1],_d,_b0.y); fma2(ACC[0][2],_d,_b1.x); fma2(ACC[0][3],_d,_b1.y); \
    _d=pk2(_a0.y,_a0.y); fma2(ACC[1][0],_d,_b0.x); fma2(ACC[1][1],_d,_b0.y); fma2(ACC[1][2],_d,_b1.x); fma2(ACC[1][3],_d,_b1.y); \
    _d=pk2(_a0.z,_a0.z); fma2(ACC[2][0],_d,_b0.x); fma2(ACC[2][1],_d,_b0.y); fma2(ACC[2][2],_d,_b1.x); fma2(ACC[2][3],_d,_b1.y); \
    _d=pk2(_a0.w,_a0.w); fma2(ACC[3][0],_d,_b0.x); fma2(ACC[3][1],_d,_b0.y); fma2(ACC[3][2],_d,_b1.x); fma2(ACC[3][3],_d,_b1.y); \
    _d=pk2(_a1.x,_a1.x); fma2(ACC[4][0],_d,_b0.x); fma2(ACC[4][1],_d,_b0.y); fma2(ACC[4][2],_d,_b1.x); fma2(ACC[4][3],_d,_b1.y); \
    _d=pk2(_a1.y,_a1.y); fma2(ACC[5][0],_d,_b0.x); fma2(ACC[5][1],_d,_b0.y); fma2(ACC[5][2],_d,_b1.x); fma2(ACC[5][3],_d,_b1.y); \
    _d=pk2(_a1.z,_a1.z); fma2(ACC[6][0],_d,_b0.x); fma2(ACC[6][1],_d,_b0.y); fma2(ACC[6][2],_d,_b1.x); fma2(ACC[6][3],_d,_b1.y); \
    _d=pk2(_a1.w,_a1.w); fma2(ACC[7][0],_d,_b0.x); fma2(ACC[7][1],_d,_b0.y); fma2(ACC[7][2],_d,_b1.x); fma2(ACC[7][3],_d,_b1.y); \
} while(0)

#define MMA_CHUNK(ACC) { _Pragma("unroll") for (int kk=0;kk<16;kk++){ FMA_KK8(ACC); } }

// unpack one acc row (4 u64 -> 8 floats)
#define UNPACK_ROW(ACC, I, F) do {                                      \
    float2 _u0=upk2(ACC[I][0]), _u1=upk2(ACC[I][1]);                    \
    float2 _u2=upk2(ACC[I][2]), _u3=upk2(ACC[I][3]);                    \
    F[0]=_u0.x; F[1]=_u0.y; F[2]=_u1.x; F[3]=_u1.y;                     \
    F[4]=_u2.x; F[5]=_u2.y; F[6]=_u3.x; F[7]=_u3.y;                     \
} while(0)

// ---------------- 1. weight-norm preprocessing --------------------------
__global__ void prep_weights(const float* __restrict__ vq, const float* __restrict__ gq,
                             const float* __restrict__ v1, const float* __restrict__ g1,
                             const float* __restrict__ v2, const float* __restrict__ g2) {
    int warp = (blockIdx.x*blockDim.x + threadIdx.x) >> 5;
    int lane = threadIdx.x & 31;
    if (warp >= 640) return;
    const float* v; const float* g; float* w; int r;
    if (warp < 384)      { v=vq; g=gq; w=g_Wqkv; r=warp; }
    else if (warp < 512) { v=v1; g=g1; w=g_W1;   r=warp-384; }
    else                 { v=v2; g=g2; w=g_W2;   r=warp-512; }
    float4 x4 = ((const float4*)(v + (size_t)r*128))[lane];
    float s = x4.x*x4.x + x4.y*x4.y + x4.z*x4.z + x4.w*x4.w;
    #pragma unroll
    for (int o=16;o;o>>=1) s += __shfl_xor_sync(0xffffffffu, s, o);
    float rn = g[r] / sqrtf(s);
    ((float4*)(w + (size_t)r*128))[lane] = make_float4(x4.x*rn, x4.y*rn, x4.z*rn, x4.w*rn);
}

// ---------------- 2. qkv projection  Y = X @ Wqkv^T + b -----------------
__global__ void __launch_bounds__(256, 2) qkv_gemm(const float* __restrict__ x,
                                                   const float* __restrict__ bias) {
    __shared__ float As[16][128];
    __shared__ float Bs[16][128];
    TDECL;
    int rt0 = blockIdx.y*128;
    int ct0 = blockIdx.x*128;   // 0,128,256
    u64 acc[8][4] = {};
    #pragma unroll 1
    for (int kc=0; kc<8; kc++) {
        int k0 = kc*16;
        LOAD_TILE(As, x      + (size_t)rt0*128 + k0);
        LOAD_TILE(Bs, g_Wqkv + (size_t)ct0*128 + k0);
        __syncthreads();
        MMA_CHUNK(acc);
        __syncthreads();
    }
    float* base = (ct0==0) ? g_Q : ((ct0==128) ? g_K : g_V);
    int c0 = tx*8;
    float bv[8];
    #pragma unroll
    for (int j=0;j<8;j++) bv[j] = bias[ct0 + c0 + j];
    #pragma unroll
    for (int i=0;i<8;i++) {
        float f[8]; UNPACK_ROW(acc, i, f);
        int row = rt0 + ty*8 + i;
        float* o = base + (size_t)row*128 + c0;
        *(float4*)o     = make_float4(f[0]+bv[0], f[1]+bv[1], f[2]+bv[2], f[3]+bv[3]);
        *(float4*)(o+4) = make_float4(f[4]+bv[4], f[5]+bv[5], f[6]+bv[6], f[7]+bv[7]);
    }
}

// ---------------- 3. row squared norms ----------------------------------
__global__ void sq_kernel(const float* __restrict__ x) {
    int warp = (blockIdx.x*blockDim.x + threadIdx.x) >> 5;
    int lane = threadIdx.x & 31;
    if (warp >= NROWS) return;
    float4 v4 = ((const float4*)(x + (size_t)warp*128))[lane];
    float s = v4.x*v4.x + v4.y*v4.y + v4.z*v4.z + v4.w*v4.w;
    #pragma unroll
    for (int o=16;o;o>>=1) s += __shfl_xor_sync(0xffffffffu, s, o);
    if (lane==0) g_sq[warp] = s;
}

// ---------------- 4. dist matrix + sigma partials (triangular) ----------
__global__ void __launch_bounds__(256, 2) dist_kernel(const float* __restrict__ x) {
    int jt = blockIdx.x, it = blockIdx.y, b = blockIdx.z;
    int bid = (b*32 + it)*32 + jt;
    __shared__ float As[16][128];
    __shared__ float Bs[16][128];
    __shared__ float red[256];
    TDECL;
    if (jt < it) { if (tid==0) g_part[bid] = 0.0f; return; }
    u64 acc[8][4] = {};
    const float* xb = x + (size_t)b*SEQ*128;
    #pragma unroll 1
    for (int kc=0; kc<8; kc++) {
        int k0 = kc*16;
        LOAD_TILE(As, xb + (size_t)it*128*128 + k0);
        LOAD_TILE(Bs, xb + (size_t)jt*128*128 + k0);
        __syncthreads();
        MMA_CHUNK(acc);
        __syncthreads();
    }
    float w = (jt==it) ? 1.0f : 2.0f;
    int i0 = it*128 + ty*8, j0 = jt*128 + tx*8;
    float sqi[8], sqj[8];
    #pragma unroll
    for (int i=0;i<8;i++) sqi[i] = g_sq[b*SEQ + i0 + i];
    #pragma unroll
    for (int j=0;j<8;j++) sqj[j] = g_sq[b*SEQ + j0 + j];
    float* Db = g_DIST + (size_t)b*SEQ*SEQ;
    float dt[8][8];          // dist, for transposed writes
    float lsum = 0.0f;
    #pragma unroll
    for (int i=0;i<8;i++) {
        float f[8]; UNPACK_ROW(acc, i, f);
        #pragma unroll
        for (int j=0;j<8;j++) {
            float d2 = sqi[i] + sqj[j] - 2.0f*f[j];
            float d = sqrtf(fmaxf(d2, 0.0f));
            dt[j][i] = d;
            f[j] = d;
            lsum += d;
        }
        float* o = Db + (size_t)(i0+i)*SEQ + j0;
        *(float4*)o     = make_float4(f[0],f[1],f[2],f[3]);
        *(float4*)(o+4) = make_float4(f[4],f[5],f[6],f[7]);
    }
    // transposed half (contiguous in gi -> vectorized)
    #pragma unroll
    for (int j=0;j<8;j++) {
        float* o = Db + (size_t)(j0+j)*SEQ + i0;
        *(float4*)o     = make_float4(dt[j][0],dt[j][1],dt[j][2],dt[j][3]);
        *(float4*)(o+4) = make_float4(dt[j][4],dt[j][5],dt[j][6],dt[j][7]);
    }
    red[tid] = lsum * w;
    __syncthreads();
    for (int o=128;o;o>>=1) { if (tid<o) red[tid] += red[tid+o]; __syncthreads(); }
    if (tid==0) g_part[bid] = red[0];
}

// ---------------- 5. finalize sigmas ------------------------------------
__global__ void finalize_kernel() {
    __shared__ double rs[256];
    int tid = threadIdx.x;
    double s = 0.0;
    for (int i=tid; i<BATCH*32*32; i+=256) s += (double)g_part[i];
    rs[tid] = s; __syncthreads();
    for (int o=128;o;o>>=1) { if (tid<o) rs[tid] += rs[tid+o]; __syncthreads(); }
    double spe_total = rs[0];
    __syncthreads();
    double sp = 0.0;
    for (int idx=tid; idx<127*127; idx+=256) {
        int dx = idx/127 - 63, dy = idx%127 - 63;
        double wgt = (double)((64-abs(dx))*(64-abs(dy)));
        sp += wgt * (double)sqrtf((float)(dx*dx + dy*dy));
    }
    rs[tid] = sp; __syncthreads();
    for (int o=128;o;o>>=1) { if (tid<o) rs[tid] += rs[tid+o]; __syncthreads(); }
    if (tid==0) {
        double nn = (double)SEQ * (double)SEQ;
        double sigma_spe = spe_total / ((double)BATCH * nn);
        double sigma_spa = rs[0] / nn;
        g_cspe = (float)(1.0 / (2.0 * sigma_spe * sigma_spe));
        g_cspa = (float)(1.0 / (2.0 * sigma_spa * sigma_spa));
    }
}

// ---------------- 6. masked logits: (Q@K^T)*mask per (b,h) --------------
__global__ void __launch_bounds__(256, 2) qk_kernel() {
    int jt = blockIdx.x, it = blockIdx.y;
    int bh = blockIdx.z;                  // b*2+h
    int b = bh >> 1, h = bh & 1;
    __shared__ float As[16][128];
    __shared__ float Bs[16][128];
    TDECL;
    u64 acc[8][4] = {};
    const float* qb = g_Q + (size_t)b*SEQ*128 + h*64;
    const float* kb = g_K + (size_t)b*SEQ*128 + h*64;
    #pragma unroll 1
    for (int kc=0; kc<4; kc++) {
        int k0 = kc*16;
        LOAD_TILE(As, qb + (size_t)it*128*128 + k0);
        LOAD_TILE(Bs, kb + (size_t)jt*128*128 + k0);
        __syncthreads();
        MMA_CHUNK(acc);
        __syncthreads();
    }
    float cspe = g_cspe, cspa = g_cspa;
    int i0 = it*128 + ty*8, j0 = jt*128 + tx*8;
    const float* Db = g_DIST + (size_t)b*SEQ*SEQ;
    float* Ob = g_DOTS + (size_t)bh*SEQ*SEQ;
    #pragma unroll
    for (int i=0;i<8;i++) {
        float f[8]; UNPACK_ROW(acc, i, f);
        int gi = i0 + i;
        int ix = gi >> 6, iy = gi & 63;
        const float* dp = Db + (size_t)gi*SEQ + j0;
        float4 d0 = *(const float4*)dp;
        float4 d1 = *(const float4*)(dp+4);
        float dd[8] = {d0.x,d0.y,d0.z,d0.w,d1.x,d1.y,d1.z,d1.w};
        #pragma unroll
        for (int j=0;j<8;j++) {
            int gj = j0 + j;
            int dx = ix - (gj >> 6), dy = iy - (gj & 63);
            float sdist = sqrtf((float)(dx*dx + dy*dy));
            float m = __expf(-(dd[j]*cspe + sdist*cspa)) * ATTN_SCALE;
            f[j] *= m;
        }
        float* o = Ob + (size_t)gi*SEQ + j0;
        *(float4*)o     = make_float4(f[0],f[1],f[2],f[3]);
        *(float4*)(o+4) = make_float4(f[4],f[5],f[6],f[7]);
    }
}

// ---------------- 7. softmax row stats ----------------------------------
__global__ void stats_kernel() {
    int r = blockIdx.x;                       // 0..16383
    size_t base = (size_t)r * SEQ;
    int tid = threadIdx.x;                    // 512 threads
    __shared__ float red[512];
    float v[8];
    float mx = -1e30f;
    #pragma unroll
    for (int s=0;s<8;s++) { v[s] = g_DOTS[base + (size_t)s*512 + tid]; mx = fmaxf(mx, v[s]); }
    red[tid] = mx; __syncthreads();
    for (int o=256;o;o>>=1) { if (tid<o) red[tid] = fmaxf(red[tid], red[tid+o]); __syncthreads(); }
    mx = red[0];
    __syncthreads();
    float sm = 0.0f;
    #pragma unroll
    for (int s=0;s<8;s++) sm += __expf(v[s] - mx);
    red[tid] = sm; __syncthreads();
    for (int o=256;o;o>>=1) { if (tid<o) red[tid] += red[tid+o]; __syncthreads(); }
    if (tid==0) { g_M[r] = mx; g_L[r] = 1.0f / red[0]; }
}

// ---------------- 8. out = softmax(dots) @ V ----------------------------
// BM=128 (i), BN=64 (=dh), BK=16 (j), 256 thr, micro 4x8
__global__ void __launch_bounds__(256, 2) pv_kernel() {
    int it = blockIdx.x;                 // 0..31 (128-row strip)
    int h  = blockIdx.y, b = blockIdx.z;
    int bh = b*2 + h;
    __shared__ float Ps[16][128];        // [j][i] exp'd probs
    __shared__ float Vs[16][64];         // [j][c]
    int tid = threadIdx.x;
    int tx8 = tid & 7, tyv = tid >> 3;   // cols tx8*8, rows tyv*4
    int pli = tid >> 1, plj = (tid&1)*8; // P loader: row i, j offset
    int vlj = tid >> 4, vlc = (tid & 15)*4; // V loader
    u64 acc[4][4] = {};
    int i0 = it*128;
    float mrow = g_M[bh*SEQ + i0 + pli];
    const float* Ob = g_DOTS + (size_t)bh*SEQ*SEQ;
    const float* vb = g_V + (size_t)b*SEQ*128 + h*64;
    #pragma unroll 1
    for (int ch=0; ch<256; ch++) {
        int j0 = ch*16;
        const float* dp = Ob + (size_t)(i0+pli)*SEQ + j0 + plj;
        float4 p0 = *(const float4*)dp;
        float4 p1 = *(const float4*)(dp+4);
        Ps[plj+0][pli]=__expf(p0.x-mrow); Ps[plj+1][pli]=__expf(p0.y-mrow);
        Ps[plj+2][pli]=__expf(p0.z-mrow); Ps[plj+3][pli]=__expf(p0.w-mrow);
        Ps[plj+4][pli]=__expf(p1.x-mrow); Ps[plj+5][pli]=__expf(p1.y-mrow);
        Ps[plj+6][pli]=__expf(p1.z-mrow); Ps[plj+7][pli]=__expf(p1.w-mrow);
        *(float4*)&Vs[vlj][vlc] = *(const float4*)(vb + (size_t)(j0+vlj)*128 + vlc);
        __syncthreads();
        #pragma unroll
        for (int kk=0;kk<16;kk++) {
            float4 _a = *(const float4*)&Ps[kk][tyv*4];
            ulonglong2 _b0 = *(const ulonglong2*)&Vs[kk][tx8*8];
            ulonglong2 _b1 = *(const ulonglong2*)&Vs[kk][tx8*8+4];
            u64 _d;
            _d=pk2(_a.x,_a.x); fma2(acc[0][0],_d,_b0.x); fma2(acc[0][1],_d,_b0.y); fma2(acc[0][2],_d,_b1.x); fma2(acc[0][3],_d,_b1.y);
            _d=pk2(_a.y,_a.y); fma2(acc[1][0],_d,_b0.x); fma2(acc[1][1],_d,_b0.y); fma2(acc[1][2],_d,_b1.x); fma2(acc[1][3],_d,_b1.y);
            _d=pk2(_a.z,_a.z); fma2(acc[2][0],_d,_b0.x); fma2(acc[2][1],_d,_b0.y); fma2(acc[2][2],_d,_b1.x); fma2(acc[2][3],_d,_b1.y);
            _d=pk2(_a.w,_a.w); fma2(acc[3][0],_d,_b0.x); fma2(acc[3][1],_d,_b0.y); fma2(acc[3][2],_d,_b1.x); fma2(acc[3][3],_d,_b1.y);
        }
        __syncthreads();
    }
    #pragma unroll
    for (int i=0;i<4;i++) {
        float f[8]; UNPACK_ROW(acc, i, f);
        int gi = i0 + tyv*4 + i;
        float li = g_L[bh*SEQ + gi];
        float* o = g_AO + ((size_t)b*SEQ + gi)*128 + h*64 + tx8*8;
        *(float4*)o     = make_float4(f[0]*li, f[1]*li, f[2]*li, f[3]*li);
        *(float4*)(o+4) = make_float4(f[4]*li, f[5]*li, f[6]*li, f[7]*li);
    }
}

// ---------------- 9/10. FeedForward GEMMs -------------------------------
__device__ __forceinline__ float gelu_exact(float v) { return v * normcdff(v); }

__global__ void __launch_bounds__(256, 2) ff_gemm(int stage, const float* __restrict__ bias,
                                                  float* __restrict__ out_final) {
    __shared__ float As[16][128];
    __shared__ float Bs[16][128];
    const float* A = (stage==0) ? g_AO : g_H1;
    const float* W = (stage==0) ? g_W1 : g_W2;
    float* out     = (stage==0) ? g_H1 : out_final;
    TDECL;
    int rt0 = blockIdx.y*128;
    u64 acc[8][4] = {};
    #pragma unroll 1
    for (int kc=0; kc<8; kc++) {
        int k0 = kc*16;
        LOAD_TILE(As, A + (size_t)rt0*128 + k0);
        LOAD_TILE(Bs, W + k0);
        __syncthreads();
        MMA_CHUNK(acc);
        __syncthreads();
    }
    int c0 = tx*8;
    float bv[8];
    #pragma unroll
    for (int j=0;j<8;j++) bv[j] = bias[c0 + j];
    #pragma unroll
    for (int i=0;i<8;i++) {
        float f[8]; UNPACK_ROW(acc, i, f);
        int row = rt0 + ty*8 + i;
        #pragma unroll
        for (int j=0;j<8;j++) {
            float v = f[j] + bv[j];
            f[j] = (stage==0) ? gelu_exact(v) : v;
        }
        float* o = out + (size_t)row*128 + c0;
        *(float4*)o     = make_float4(f[0],f[1],f[2],f[3]);
        *(float4*)(o+4) = make_float4(f[4],f[5],f[6],f[7]);
    }
}

// ---------------- launch ------------------------------------------------
extern "C" void kernel_launch(void* const* d_in, const int* in_sizes, int n_in,
                              void* d_out, int out_size) {
    (void)in_sizes; (void)n_in; (void)out_size;
    const float* x     = (const float*)d_in[0];
    const float* v_qkv = (const float*)d_in[1];
    const float* gq    = (const float*)d_in[2];
    const float* b_qkv = (const float*)d_in[3];
    const float* v_ff1 = (const float*)d_in[4];
    const float* g_ff1 = (const float*)d_in[5];
    const float* b_ff1 = (const float*)d_in[6];
    const float* v_ff2 = (const float*)d_in[7];
    const float* g_ff2 = (const float*)d_in[8];
    const float* b_ff2 = (const float*)d_in[9];
    float* out = (float*)d_out;

    prep_weights<<<80, 256>>>(v_qkv, gq, v_ff1, g_ff1, v_ff2, g_ff2);
    qkv_gemm<<<dim3(3, 64), 256>>>(x, b_qkv);
    sq_kernel<<<1024, 256>>>(x);
    dist_kernel<<<dim3(32, 32, BATCH), 256>>>(x);
    finalize_kernel<<<1, 256>>>();
    qk_kernel<<<dim3(32, 32, BATCH*HEADS), 256>>>();
    stats_kernel<<<BATCH*HEADS*SEQ, 512>>>();
    pv_kernel<<<dim3(32, HEADS, BATCH), 256>>>();
    ff_gemm<<<dim3(1, 64), 256>>>(0, b_ff1, nullptr);
    ff_gemm<<<dim3(1, 64), 256>>>(1, b_ff2, out);
}